// round 1
// baseline (speedup 1.0000x reference)
#include <cuda_runtime.h>
#include <math.h>

#define BATCH 2
#define SEQ   2048
#define DM    1024
#define NH    16
#define DH    64

// Scratch (allocation-free rule: __device__ globals)
__device__ float g_q[BATCH*SEQ*DM];
__device__ float g_k[BATCH*SEQ*DM];
__device__ float g_v[BATCH*SEQ*DM];
__device__ float g_attn[BATCH*SEQ*DM];

// ---------------------------------------------------------------------------
// C[M,N] = A[M,K] @ W[N,K]^T + bias[N]
// 64x64 tile, BK=16, 256 threads, 4x4 micro-tile per thread.
// ---------------------------------------------------------------------------
__global__ void gemm_bias_kernel(const float* __restrict__ A,
                                 const float* __restrict__ W,
                                 const float* __restrict__ bias,
                                 float* __restrict__ C,
                                 int M, int N, int K) {
    __shared__ float As[16][65];   // [k][m], padded -> conflict-free
    __shared__ float Bs[16][65];   // [k][n]
    const int tid = threadIdx.x;
    const int tx = tid & 15;       // n-fragment
    const int ty = tid >> 4;       // m-fragment
    const int m0 = blockIdx.y * 64;
    const int n0 = blockIdx.x * 64;

    float acc[4][4];
    #pragma unroll
    for (int i = 0; i < 4; i++)
        #pragma unroll
        for (int j = 0; j < 4; j++) acc[i][j] = 0.f;

    const int lk = tid & 15;   // k within tile
    const int lr = tid >> 4;   // row base

    for (int k0 = 0; k0 < K; k0 += 16) {
        #pragma unroll
        for (int rr = 0; rr < 4; rr++) {
            As[lk][lr + 16*rr] = A[(size_t)(m0 + lr + 16*rr) * K + k0 + lk];
            Bs[lk][lr + 16*rr] = W[(size_t)(n0 + lr + 16*rr) * K + k0 + lk];
        }
        __syncthreads();
        #pragma unroll
        for (int kk = 0; kk < 16; kk++) {
            float a[4], b[4];
            #pragma unroll
            for (int i = 0; i < 4; i++) a[i] = As[kk][ty + 16*i];
            #pragma unroll
            for (int j = 0; j < 4; j++) b[j] = Bs[kk][tx + 16*j];
            #pragma unroll
            for (int i = 0; i < 4; i++)
                #pragma unroll
                for (int j = 0; j < 4; j++)
                    acc[i][j] = fmaf(a[i], b[j], acc[i][j]);
        }
        __syncthreads();
    }
    #pragma unroll
    for (int i = 0; i < 4; i++)
        #pragma unroll
        for (int j = 0; j < 4; j++)
            C[(size_t)(m0 + ty + 16*i) * N + n0 + tx + 16*j] =
                acc[i][j] + bias[n0 + tx + 16*j];
}

// ---------------------------------------------------------------------------
// Flash attention: one CTA per (b, h, 64-query tile). 256 threads.
// 4 threads per query row; interleaved column ownership col = cg + 4*c.
// Online softmax; P exchanged via shfl within the 4-lane group.
// ---------------------------------------------------------------------------
#define SMS 68   // smem row stride (floats)

__global__ void attn_kernel(const float* __restrict__ q,
                            const float* __restrict__ k,
                            const float* __restrict__ v,
                            const int*   __restrict__ mask,
                            float* __restrict__ out) {
    extern __shared__ float smem[];
    float* Qs = smem;                     // [64][68]
    float* Ks = smem + 64 * SMS;          // [64][68]
    float* Vs = smem + 2 * 64 * SMS;      // [64][68]
    float* Mb = smem + 3 * 64 * SMS;      // [64] mask flags (0/1)

    const int b  = blockIdx.z;
    const int h  = blockIdx.y;
    const int q0 = blockIdx.x * 64;
    const int tid = threadIdx.x;
    const int r  = tid >> 2;   // query row within tile
    const int cg = tid & 3;    // column group

    // Load Q tile (coalesced)
    for (int i = tid; i < 64 * DH; i += 256) {
        int row = i >> 6, d = i & 63;
        Qs[row * SMS + d] = q[((size_t)(b * SEQ + q0 + row)) * DM + h * DH + d];
    }

    float m = -1e30f, l = 0.f;
    float acc[16];
    #pragma unroll
    for (int c = 0; c < 16; c++) acc[c] = 0.f;

    for (int j0 = 0; j0 < SEQ; j0 += 64) {
        __syncthreads();   // protect previous tile's consumers
        for (int i = tid; i < 64 * DH; i += 256) {
            int row = i >> 6, d = i & 63;
            size_t gidx = ((size_t)(b * SEQ + j0 + row)) * DM + h * DH + d;
            Ks[row * SMS + d] = k[gidx];
            Vs[row * SMS + d] = v[gidx];
        }
        if (tid < 64) Mb[tid] = (float)mask[b * SEQ + j0 + tid];
        __syncthreads();

        // scores for my 16 columns (col = cg + 4c)
        float dotv[16];
        #pragma unroll
        for (int c = 0; c < 16; c++) dotv[c] = 0.f;
        for (int d = 0; d < DH; d++) {
            float qv = Qs[r * SMS + d];
            #pragma unroll
            for (int c = 0; c < 16; c++)
                dotv[c] = fmaf(qv, Ks[(cg + 4 * c) * SMS + d], dotv[c]);
        }

        float tmax = -1e30f;
        #pragma unroll
        for (int c = 0; c < 16; c++) {
            float s = dotv[c] * 0.125f;               // 1/sqrt(64)
            if (Mb[cg + 4 * c] == 0.f) s = -1e9f;     // exact reference masking
            dotv[c] = s;
            tmax = fmaxf(tmax, s);
        }
        tmax = fmaxf(tmax, __shfl_xor_sync(0xffffffffu, tmax, 1));
        tmax = fmaxf(tmax, __shfl_xor_sync(0xffffffffu, tmax, 2));

        float m_new = fmaxf(m, tmax);
        float alpha = __expf(m - m_new);
        float psum = 0.f;
        #pragma unroll
        for (int c = 0; c < 16; c++) {
            dotv[c] = __expf(dotv[c] - m_new);
            psum += dotv[c];
        }
        psum += __shfl_xor_sync(0xffffffffu, psum, 1);
        psum += __shfl_xor_sync(0xffffffffu, psum, 2);
        l = l * alpha + psum;
        m = m_new;
        #pragma unroll
        for (int c = 0; c < 16; c++) acc[c] *= alpha;

        // PV: exchange p across the 4-lane group, accumulate my 16 out-cols
        #pragma unroll 4
        for (int c2 = 0; c2 < 16; c2++) {
            #pragma unroll
            for (int grp = 0; grp < 4; grp++) {
                int col = grp + 4 * c2;
                float p = __shfl_sync(0xffffffffu, dotv[c2], grp, 4);
                #pragma unroll
                for (int cc = 0; cc < 16; cc++)
                    acc[cc] = fmaf(p, Vs[col * SMS + cg + 4 * cc], acc[cc]);
            }
        }
    }

    float inv = 1.f / l;
    #pragma unroll
    for (int c = 0; c < 16; c++)
        out[((size_t)(b * SEQ + q0 + r)) * DM + h * DH + cg + 4 * c] = acc[c] * inv;
}

// ---------------------------------------------------------------------------
extern "C" void kernel_launch(void* const* d_in, const int* in_sizes, int n_in,
                              void* d_out, int out_size) {
    const float* query = (const float*)d_in[0];
    const float* key_t = (const float*)d_in[1];
    const float* value = (const float*)d_in[2];
    const int*   mask  = (const int*)  d_in[3];
    const float* Wq = (const float*)d_in[4];
    const float* bq = (const float*)d_in[5];
    const float* Wk = (const float*)d_in[6];
    const float* bk = (const float*)d_in[7];
    const float* Wv = (const float*)d_in[8];
    const float* bv = (const float*)d_in[9];
    const float* Wo = (const float*)d_in[10];
    const float* bo = (const float*)d_in[11];
    float* out = (float*)d_out;

    float *q, *k, *v, *attn;
    cudaGetSymbolAddress((void**)&q,    g_q);
    cudaGetSymbolAddress((void**)&k,    g_k);
    cudaGetSymbolAddress((void**)&v,    g_v);
    cudaGetSymbolAddress((void**)&attn, g_attn);

    const int M = BATCH * SEQ;       // 4096
    dim3 ggrid(DM / 64, M / 64);     // (16, 64)

    gemm_bias_kernel<<<ggrid, 256>>>(query, Wq, bq, q, M, DM, DM);
    gemm_bias_kernel<<<ggrid, 256>>>(key_t, Wk, bk, k, M, DM, DM);
    gemm_bias_kernel<<<ggrid, 256>>>(value, Wv, bv, v, M, DM, DM);

    const int attn_smem = (3 * 64 * SMS + 64) * (int)sizeof(float);  // ~52.5 KB
    cudaFuncSetAttribute(attn_kernel,
                         cudaFuncAttributeMaxDynamicSharedMemorySize, attn_smem);
    dim3 agrid(SEQ / 64, NH, BATCH); // (32, 16, 2)
    attn_kernel<<<agrid, 256, attn_smem>>>(q, k, v, mask, attn);

    gemm_bias_kernel<<<ggrid, 256>>>(attn, Wo, bo, out, M, DM, DM);
}